// round 7
// baseline (speedup 1.0000x reference)
#include <cuda_runtime.h>
#include <math.h>

#define D          2048
#define B_MAX      32768
#define T1_ROWS    16          // K1: rows per 256-thread block (2 per warp)
#define T1_THREADS 256
#define T2_ROWS    16          // K2: rows per 128-thread block
#define T2_THREADS 128
#define INV_SQRT2_F 0.70710678118654752440f
#define PI_F        3.14159265358979323846f

// Inter-kernel scratch: raw dot products, one float4 per row.
__device__ float4 araw_g[B_MAX];

__device__ __forceinline__ float2 cmul(float2 a, float2 b) {
    return make_float2(fmaf(a.x, b.x, -a.y * b.y), fmaf(a.x, b.y, a.y * b.x));
}

// ============================================================================
// K1: araw[row] = x[row] . W_pre[q]   — read streamer (measured 48.8us, keep)
// ============================================================================
__global__ __launch_bounds__(T1_THREADS, 5)
void k1_dot(const float* __restrict__ x, const float* __restrict__ W_pre)
{
    __shared__ __align__(16) float wq[4][D];      // 32 KB

    const int tid  = threadIdx.x;
    const int lane = tid & 31;
    const int warp = tid >> 5;
    const size_t tile_base = (size_t)blockIdx.x * T1_ROWS;

    {   // stage W_pre
        const float4* wsrc = (const float4*)W_pre;
        float4*       wdst = (float4*)wq;
#pragma unroll
        for (int k = 0; k < (4 * D / 4) / T1_THREADS; k++)
            wdst[k * T1_THREADS + tid] = wsrc[k * T1_THREADS + tid];
    }
    __syncthreads();

    const int r0 = warp * 2;
    const float4* xp = (const float4*)x + (tile_base + r0) * (D / 4) + lane;

    float acc[2][4] = {};
#pragma unroll
    for (int i = 0; i < D / 128; i++) {
        float4 xv[2];
#pragma unroll
        for (int r = 0; r < 2; r++) xv[r] = __ldcs(xp + r * (D / 4) + i * 32);
        float4 wv[4];
#pragma unroll
        for (int q = 0; q < 4; q++)
            wv[q] = *(const float4*)&wq[q][i * 128 + lane * 4];
#pragma unroll
        for (int r = 0; r < 2; r++)
#pragma unroll
            for (int q = 0; q < 4; q++)
                acc[r][q] = fmaf(xv[r].x, wv[q].x,
                            fmaf(xv[r].y, wv[q].y,
                            fmaf(xv[r].z, wv[q].z,
                            fmaf(xv[r].w, wv[q].w, acc[r][q]))));
    }
#pragma unroll
    for (int r = 0; r < 2; r++)
#pragma unroll
        for (int q = 0; q < 4; q++)
#pragma unroll
            for (int o = 16; o; o >>= 1)
                acc[r][q] += __shfl_xor_sync(0xffffffffu, acc[r][q], o);
    if (lane == 0) {
#pragma unroll
        for (int r = 0; r < 2; r++)
            araw_g[tile_base + r0 + r] =
                make_float4(acc[r][0], acc[r][1], acc[r][2], acc[r][3]);
    }
}

// ============================================================================
// K2: circuit (warp 0, 16 lanes) + out = z.W_post^T + b_post (write streamer)
// 128 thr, 16 rows, launch_bounds(128,12) -> 42 regs: streamer fits (~34, no
// spill); circuit-path spill is confined to 16/128 threads (harmless).
// 12 CTAs/SM -> 48 warps = 75% occ.
// ============================================================================
__global__ __launch_bounds__(T2_THREADS, 12)
void k2_circuit_out(const float* __restrict__ b_pre,
                    const float* __restrict__ q_weights,
                    const float* __restrict__ W_post,
                    const float* __restrict__ b_post,
                    float* __restrict__ out)
{
    __shared__ float4 zs[T2_ROWS];
    __shared__ float2 rotg[2][4][4];

    const int tid = threadIdx.x;
    const size_t tile_base = (size_t)blockIdx.x * T2_ROWS;

    if (tid < 32) {                               // circuit lives in warp 0
        if (tid < 8) {                            // batch-constant Rot gates
            const int l = tid >> 2, q = tid & 3;
            const float phi = q_weights[(l * 4 + q) * 3 + 0];
            const float th  = q_weights[(l * 4 + q) * 3 + 1];
            const float om  = q_weights[(l * 4 + q) * 3 + 2];
            float c, s;   sincosf(0.5f * th, &s, &c);
            float sp, cp; sincosf(0.5f * (phi + om), &sp, &cp);
            float sm, cm; sincosf(0.5f * (phi - om), &sm, &cm);
            rotg[l][q][0] = make_float2( cp * c, -sp * c);   // ep*c
            rotg[l][q][1] = make_float2(-cm * s, -sm * s);   // -em*s
            rotg[l][q][2] = make_float2( cm * s, -sm * s);   // conj(em)*s
            rotg[l][q][3] = make_float2( cp * c,  sp * c);   // conj(ep)*c
        }
        __syncwarp();

        if (tid < T2_ROWS) {                      // one row per lane
            float4 ar = araw_g[tile_base + tid];
            ar.x += __ldg(b_pre + 0);
            ar.y += __ldg(b_pre + 1);
            ar.z += __ldg(b_pre + 2);
            ar.w += __ldg(b_pre + 3);
            const float f[4] = { PI_F * tanhf(ar.x), PI_F * tanhf(ar.y),
                                 PI_F * tanhf(ar.z), PI_F * tanhf(ar.w) };

            float2 v0[4], v1[4];
#pragma unroll
            for (int w = 0; w < 4; w++) {
                float sy, cy; sincosf(0.5f * atanf(f[w]), &sy, &cy);
                float sz, cz; sincosf(0.5f * atanf(f[w] * f[w]), &sz, &cz);
                const float a0 = INV_SQRT2_F * (cy - sy);
                const float a1 = INV_SQRT2_F * (cy + sy);
                v0[w] = make_float2(a0 * cz, -a0 * sz);
                v1[w] = make_float2(a1 * cz,  a1 * sz);
            }
            float2 st[16];
            {
                float2 t2[2] = { v0[0], v1[0] };
                float2 t4[4];
#pragma unroll
                for (int a = 0; a < 2; a++) { t4[a*2+0] = cmul(t2[a], v0[1]); t4[a*2+1] = cmul(t2[a], v1[1]); }
                float2 t8[8];
#pragma unroll
                for (int a = 0; a < 4; a++) { t8[a*2+0] = cmul(t4[a], v0[2]); t8[a*2+1] = cmul(t4[a], v1[2]); }
#pragma unroll
                for (int a = 0; a < 8; a++) { st[a*2+0] = cmul(t8[a], v0[3]); st[a*2+1] = cmul(t8[a], v1[3]); }
            }
#pragma unroll
            for (int l = 0; l < 2; l++) {
#pragma unroll
                for (int c = 0; c < 4; c++) {     // CNOT ring: register permutation
                    const int t  = (c + 1) & 3;
                    const int pc = 3 - c, pt = 3 - t;
                    float2 tmp[16];
#pragma unroll
                    for (int i = 0; i < 16; i++)
                        tmp[i] = st[((i >> pc) & 1) ? (i ^ (1 << pt)) : i];
#pragma unroll
                    for (int i = 0; i < 16; i++) st[i] = tmp[i];
                }
#pragma unroll
                for (int q = 0; q < 4; q++) {
                    const float2 g00 = rotg[l][q][0], g01 = rotg[l][q][1];
                    const float2 g10 = rotg[l][q][2], g11 = rotg[l][q][3];
                    const int m = 1 << (3 - q);
#pragma unroll
                    for (int i = 0; i < 16; i++) {
                        if ((i & m) == 0) {
                            const float2 s0 = st[i], s1 = st[i | m];
                            const float2 a = cmul(g00, s0), b = cmul(g01, s1);
                            const float2 c2 = cmul(g10, s0), d = cmul(g11, s1);
                            st[i]     = make_float2(a.x + b.x,  a.y + b.y);
                            st[i | m] = make_float2(c2.x + d.x, c2.y + d.y);
                        }
                    }
                }
            }
            float z[4] = {0.f, 0.f, 0.f, 0.f};
#pragma unroll
            for (int i = 0; i < 16; i++) {
                const float p = st[i].x * st[i].x + st[i].y * st[i].y;
#pragma unroll
                for (int w = 0; w < 4; w++)
                    z[w] += ((i >> (3 - w)) & 1) ? -p : p;
            }
            zs[tid] = make_float4(z[0], z[1], z[2], z[3]);
        }
    }
    __syncthreads();

    // ---- write streamer: 4 chunks of 128 float4 cols, chunk regs transient ----
    const float4* W4 = (const float4*)W_post;
    const float4* B4 = (const float4*)b_post;
#pragma unroll
    for (int j = 0; j < 4; j++) {
        const int g  = j * T2_THREADS + tid;      // output float4 index in row
        const int c0 = g * 4;
        const float4 w0 = __ldg(W4 + c0 + 0);
        const float4 w1 = __ldg(W4 + c0 + 1);
        const float4 w2 = __ldg(W4 + c0 + 2);
        const float4 w3 = __ldg(W4 + c0 + 3);
        const float4 bv = __ldg(B4 + g);
        float4* op = (float4*)out + tile_base * (D / 4) + g;
#pragma unroll
        for (int r = 0; r < T2_ROWS; r++) {
            const float4 z = zs[r];
            float4 o;
            o.x = fmaf(z.x, w0.x, fmaf(z.y, w0.y, fmaf(z.z, w0.z, fmaf(z.w, w0.w, bv.x))));
            o.y = fmaf(z.x, w1.x, fmaf(z.y, w1.y, fmaf(z.z, w1.z, fmaf(z.w, w1.w, bv.y))));
            o.z = fmaf(z.x, w2.x, fmaf(z.y, w2.y, fmaf(z.z, w2.z, fmaf(z.w, w2.w, bv.z))));
            o.w = fmaf(z.x, w3.x, fmaf(z.y, w3.y, fmaf(z.z, w3.z, fmaf(z.w, w3.w, bv.w))));
            op[r * (D / 4)] = o;
        }
    }
}

extern "C" void kernel_launch(void* const* d_in, const int* in_sizes, int n_in,
                              void* d_out, int out_size)
{
    const float* x      = (const float*)d_in[0];
    const float* W_pre  = (const float*)d_in[1];
    const float* b_pre  = (const float*)d_in[2];
    const float* qw     = (const float*)d_in[3];
    const float* W_post = (const float*)d_in[4];
    const float* b_post = (const float*)d_in[5];
    float* out = (float*)d_out;

    const int rows = in_sizes[0] / D;             // 32768
    k1_dot<<<rows / T1_ROWS, T1_THREADS>>>(x, W_pre);
    k2_circuit_out<<<rows / T2_ROWS, T2_THREADS>>>(b_pre, qw, W_post, b_post, out);
}

// round 8
// speedup vs baseline: 1.9722x; 1.9722x over previous
#include <cuda_runtime.h>
#include <math.h>

#define D          2048
#define B_MAX      32768
#define T1_ROWS    16          // K1: rows per 256-thread block (2 per warp)
#define T1_THREADS 256
#define TC_THREADS 256         // k_circ: 1 row per thread
#define TO_ROWS    16          // k_out: rows per 128-thread block
#define TO_THREADS 128
#define INV_SQRT2_F 0.70710678118654752440f
#define PI_F        3.14159265358979323846f

// Inter-kernel scratch
__device__ float4 araw_g[B_MAX];   // raw dot products
__device__ float4 z_g[B_MAX];      // circuit outputs

__device__ __forceinline__ float2 cmul(float2 a, float2 b) {
    return make_float2(fmaf(a.x, b.x, -a.y * b.y), fmaf(a.x, b.y, a.y * b.x));
}

// ============================================================================
// K1: araw[row] = x[row] . W_pre[q]  — read streamer (measured 48.8us, frozen)
// ============================================================================
__global__ __launch_bounds__(T1_THREADS, 5)
void k1_dot(const float* __restrict__ x, const float* __restrict__ W_pre)
{
    __shared__ __align__(16) float wq[4][D];      // 32 KB

    const int tid  = threadIdx.x;
    const int lane = tid & 31;
    const int warp = tid >> 5;
    const size_t tile_base = (size_t)blockIdx.x * T1_ROWS;

    {   // stage W_pre
        const float4* wsrc = (const float4*)W_pre;
        float4*       wdst = (float4*)wq;
#pragma unroll
        for (int k = 0; k < (4 * D / 4) / T1_THREADS; k++)
            wdst[k * T1_THREADS + tid] = wsrc[k * T1_THREADS + tid];
    }
    __syncthreads();

    const int r0 = warp * 2;
    const float4* xp = (const float4*)x + (tile_base + r0) * (D / 4) + lane;

    float acc[2][4] = {};
#pragma unroll
    for (int i = 0; i < D / 128; i++) {
        float4 xv[2];
#pragma unroll
        for (int r = 0; r < 2; r++) xv[r] = __ldcs(xp + r * (D / 4) + i * 32);
        float4 wv[4];
#pragma unroll
        for (int q = 0; q < 4; q++)
            wv[q] = *(const float4*)&wq[q][i * 128 + lane * 4];
#pragma unroll
        for (int r = 0; r < 2; r++)
#pragma unroll
            for (int q = 0; q < 4; q++)
                acc[r][q] = fmaf(xv[r].x, wv[q].x,
                            fmaf(xv[r].y, wv[q].y,
                            fmaf(xv[r].z, wv[q].z,
                            fmaf(xv[r].w, wv[q].w, acc[r][q]))));
    }
#pragma unroll
    for (int r = 0; r < 2; r++)
#pragma unroll
        for (int q = 0; q < 4; q++)
#pragma unroll
            for (int o = 16; o; o >>= 1)
                acc[r][q] += __shfl_xor_sync(0xffffffffu, acc[r][q], o);
    if (lane == 0) {
#pragma unroll
        for (int r = 0; r < 2; r++)
            araw_g[tile_base + r0 + r] =
                make_float4(acc[r][0], acc[r][1], acc[r][2], acc[r][3]);
    }
}

// ============================================================================
// k_circ: z[row] = circuit(araw[row]).  One thread per row, UNCAPPED regs so
// the 16-amplitude state is fully register-resident.  ~3-5us total.
// ============================================================================
__global__ void k_circ(const float* __restrict__ b_pre,
                       const float* __restrict__ q_weights)
{
    __shared__ float2 rotg[2][4][4];
    const int tid = threadIdx.x;

    if (tid < 8) {                                // batch-constant Rot gates
        const int l = tid >> 2, q = tid & 3;
        const float phi = q_weights[(l * 4 + q) * 3 + 0];
        const float th  = q_weights[(l * 4 + q) * 3 + 1];
        const float om  = q_weights[(l * 4 + q) * 3 + 2];
        float c, s;   sincosf(0.5f * th, &s, &c);
        float sp, cp; sincosf(0.5f * (phi + om), &sp, &cp);
        float sm, cm; sincosf(0.5f * (phi - om), &sm, &cm);
        rotg[l][q][0] = make_float2( cp * c, -sp * c);   // ep*c
        rotg[l][q][1] = make_float2(-cm * s, -sm * s);   // -em*s
        rotg[l][q][2] = make_float2( cm * s, -sm * s);   // conj(em)*s
        rotg[l][q][3] = make_float2( cp * c,  sp * c);   // conj(ep)*c
    }
    __syncthreads();

    const int row = blockIdx.x * TC_THREADS + tid;

    float4 ar = araw_g[row];
    ar.x += __ldg(b_pre + 0);
    ar.y += __ldg(b_pre + 1);
    ar.z += __ldg(b_pre + 2);
    ar.w += __ldg(b_pre + 3);
    const float f[4] = { PI_F * tanhf(ar.x), PI_F * tanhf(ar.y),
                         PI_F * tanhf(ar.z), PI_F * tanhf(ar.w) };

    float2 v0[4], v1[4];
#pragma unroll
    for (int w = 0; w < 4; w++) {
        float sy, cy; sincosf(0.5f * atanf(f[w]), &sy, &cy);
        float sz, cz; sincosf(0.5f * atanf(f[w] * f[w]), &sz, &cz);
        const float a0 = INV_SQRT2_F * (cy - sy);
        const float a1 = INV_SQRT2_F * (cy + sy);
        v0[w] = make_float2(a0 * cz, -a0 * sz);
        v1[w] = make_float2(a1 * cz,  a1 * sz);
    }
    float2 st[16];
    {
        float2 t2[2] = { v0[0], v1[0] };
        float2 t4[4];
#pragma unroll
        for (int a = 0; a < 2; a++) { t4[a*2+0] = cmul(t2[a], v0[1]); t4[a*2+1] = cmul(t2[a], v1[1]); }
        float2 t8[8];
#pragma unroll
        for (int a = 0; a < 4; a++) { t8[a*2+0] = cmul(t4[a], v0[2]); t8[a*2+1] = cmul(t4[a], v1[2]); }
#pragma unroll
        for (int a = 0; a < 8; a++) { st[a*2+0] = cmul(t8[a], v0[3]); st[a*2+1] = cmul(t8[a], v1[3]); }
    }
#pragma unroll
    for (int l = 0; l < 2; l++) {
#pragma unroll
        for (int c = 0; c < 4; c++) {             // CNOT ring: register permutation
            const int t  = (c + 1) & 3;
            const int pc = 3 - c, pt = 3 - t;
            float2 tmp[16];
#pragma unroll
            for (int i = 0; i < 16; i++)
                tmp[i] = st[((i >> pc) & 1) ? (i ^ (1 << pt)) : i];
#pragma unroll
            for (int i = 0; i < 16; i++) st[i] = tmp[i];
        }
#pragma unroll
        for (int q = 0; q < 4; q++) {
            const float2 g00 = rotg[l][q][0], g01 = rotg[l][q][1];
            const float2 g10 = rotg[l][q][2], g11 = rotg[l][q][3];
            const int m = 1 << (3 - q);
#pragma unroll
            for (int i = 0; i < 16; i++) {
                if ((i & m) == 0) {
                    const float2 s0 = st[i], s1 = st[i | m];
                    const float2 a = cmul(g00, s0), b = cmul(g01, s1);
                    const float2 c2 = cmul(g10, s0), d = cmul(g11, s1);
                    st[i]     = make_float2(a.x + b.x,  a.y + b.y);
                    st[i | m] = make_float2(c2.x + d.x, c2.y + d.y);
                }
            }
        }
    }
    float z[4] = {0.f, 0.f, 0.f, 0.f};
#pragma unroll
    for (int i = 0; i < 16; i++) {
        const float p = st[i].x * st[i].x + st[i].y * st[i].y;
#pragma unroll
        for (int w = 0; w < 4; w++)
            z[w] += ((i >> (3 - w)) & 1) ? -p : p;
    }
    z_g[row] = make_float4(z[0], z[1], z[2], z[3]);
}

// ============================================================================
// k_out: out[row] = z[row].W_post^T + b_post — pure write streamer.
// NO register cap: the W-chunk registers must never spill (spill costs ~1GB
// of phantom DRAM traffic, proven in R5/R6/R7).
// ============================================================================
__global__ void k_out(const float* __restrict__ W_post,
                      const float* __restrict__ b_post,
                      float* __restrict__ out)
{
    __shared__ float4 zs[TO_ROWS];
    const int tid = threadIdx.x;
    const size_t tile_base = (size_t)blockIdx.x * TO_ROWS;

    if (tid < TO_ROWS) zs[tid] = z_g[tile_base + tid];
    __syncthreads();

    const float4* W4 = (const float4*)W_post;
    const float4* B4 = (const float4*)b_post;
#pragma unroll
    for (int j = 0; j < 4; j++) {                 // 4 chunks of 128 float4 cols
        const int g  = j * TO_THREADS + tid;      // output float4 index in row
        const int c0 = g * 4;
        const float4 w0 = __ldg(W4 + c0 + 0);
        const float4 w1 = __ldg(W4 + c0 + 1);
        const float4 w2 = __ldg(W4 + c0 + 2);
        const float4 w3 = __ldg(W4 + c0 + 3);
        const float4 bv = __ldg(B4 + g);
        float4* op = (float4*)out + tile_base * (D / 4) + g;
#pragma unroll
        for (int r = 0; r < TO_ROWS; r++) {
            const float4 z = zs[r];
            float4 o;
            o.x = fmaf(z.x, w0.x, fmaf(z.y, w0.y, fmaf(z.z, w0.z, fmaf(z.w, w0.w, bv.x))));
            o.y = fmaf(z.x, w1.x, fmaf(z.y, w1.y, fmaf(z.z, w1.z, fmaf(z.w, w1.w, bv.y))));
            o.z = fmaf(z.x, w2.x, fmaf(z.y, w2.y, fmaf(z.z, w2.z, fmaf(z.w, w2.w, bv.z))));
            o.w = fmaf(z.x, w3.x, fmaf(z.y, w3.y, fmaf(z.z, w3.z, fmaf(z.w, w3.w, bv.w))));
            op[r * (D / 4)] = o;
        }
    }
}

extern "C" void kernel_launch(void* const* d_in, const int* in_sizes, int n_in,
                              void* d_out, int out_size)
{
    const float* x      = (const float*)d_in[0];
    const float* W_pre  = (const float*)d_in[1];
    const float* b_pre  = (const float*)d_in[2];
    const float* qw     = (const float*)d_in[3];
    const float* W_post = (const float*)d_in[4];
    const float* b_post = (const float*)d_in[5];
    float* out = (float*)d_out;

    const int rows = in_sizes[0] / D;             // 32768
    k1_dot<<<rows / T1_ROWS, T1_THREADS>>>(x, W_pre);
    k_circ<<<rows / TC_THREADS, TC_THREADS>>>(b_pre, qw);
    k_out<<<rows / TO_ROWS, TO_THREADS>>>(W_post, b_post, out);
}